// round 1
// baseline (speedup 1.0000x reference)
#include <cuda_runtime.h>

// Problem constants (fixed by setup_inputs)
#define BS      64
#define C_TS    128
#define C_CTS   256
#define T_LEN   2048
#define N_CAT   32
#define N_CONT  64

#define MASK_P    0.15f
#define REPLACE_P 0.80f
#define RAND_HI   0.90f   // REPLACE_P + RANDOM_P

// ---------------------------------------------------------------------------
// Time-series masking: x [BS, C, T], decisions over [BS, T] broadcast to C.
// Thread handles 4 consecutive t in one (b, c) row. float4 everywhere.
// ---------------------------------------------------------------------------
__global__ void mask_ts_kernel(const float* __restrict__ x,
                               const float* __restrict__ u_mask,
                               const float* __restrict__ u_act,
                               const int*   __restrict__ r_idx,
                               float* __restrict__ out,
                               int C)
{
    long gid = (long)blockIdx.x * blockDim.x + threadIdx.x;
    const int groups_per_row = T_LEN / 4;
    int  t4 = (int)(gid % groups_per_row);
    long bc = gid / groups_per_row;          // b*C + c
    int  b  = (int)(bc / C);
    int  t0 = t4 * 4;

    const long  brow = (long)b * T_LEN + t0;
    const float4 um4 = *(const float4*)(u_mask + brow);
    const float4 ua4 = *(const float4*)(u_act  + brow);
    const int4   r4  = *(const int4*)  (r_idx  + brow);

    const float* row = x + bc * T_LEN;
    float4 x4 = *(const float4*)(row + t0);

    float xv[4] = {x4.x, x4.y, x4.z, x4.w};
    float um[4] = {um4.x, um4.y, um4.z, um4.w};
    float ua[4] = {ua4.x, ua4.y, ua4.z, ua4.w};
    int   rv[4] = {r4.x, r4.y, r4.z, r4.w};

    float o[4];
#pragma unroll
    for (int i = 0; i < 4; i++) {
        float v = xv[i];
        if (um[i] < MASK_P) {
            if (ua[i] < REPLACE_P)      v = 0.0f;
            else if (ua[i] < RAND_HI)   v = __ldg(row + rv[i]);   // swap within row
        }
        o[i] = v;
    }

    float4 o4 = make_float4(o[0], o[1], o[2], o[3]);
    *(float4*)(out + bc * T_LEN + t0) = o4;
}

// ---------------------------------------------------------------------------
// Static categorical + continuous masking. Single block.
// cat:  out = rep ? 0 : (rnd ? r_cat_val : x_cat)           (emitted as f32)
// cont: out = rep ? column_mean : (rnd ? x[r_idx, j] : x)
// ---------------------------------------------------------------------------
__global__ void mask_static_kernel(const int*   __restrict__ x_cat,
                                   const float* __restrict__ x_cont,
                                   const float* __restrict__ u_cat_mask,
                                   const float* __restrict__ u_cat_act,
                                   const int*   __restrict__ r_cat_val,
                                   const float* __restrict__ u_cont_mask,
                                   const float* __restrict__ u_cont_act,
                                   const int*   __restrict__ r_cont_idx,
                                   float* __restrict__ out_cat,
                                   float* __restrict__ out_cont)
{
    __shared__ float means[N_CONT];
    int tid = threadIdx.x;

    if (tid < N_CONT) {
        float s = 0.0f;
        for (int b = 0; b < BS; b++) s += x_cont[b * N_CONT + tid];
        means[tid] = s * (1.0f / BS);
    }
    __syncthreads();

    // categorical: BS*N_CAT = 2048 elements
    for (int i = tid; i < BS * N_CAT; i += blockDim.x) {
        float um = u_cat_mask[i];
        float ua = u_cat_act[i];
        int v = x_cat[i];
        if (um < MASK_P) {
            if (ua < REPLACE_P)    v = 0;
            else if (ua < RAND_HI) v = r_cat_val[i];
        }
        out_cat[i] = (float)v;
    }

    // continuous: BS*N_CONT = 4096 elements
    for (int i = tid; i < BS * N_CONT; i += blockDim.x) {
        int j = i % N_CONT;
        float um = u_cont_mask[i];
        float ua = u_cont_act[i];
        float v = x_cont[i];
        if (um < MASK_P) {
            if (ua < REPLACE_P)    v = means[j];
            else if (ua < RAND_HI) v = x_cont[r_cont_idx[i] * N_CONT + j];
        }
        out_cont[i] = v;
    }
}

// ---------------------------------------------------------------------------
// Launch: inputs in metadata order:
//  0 x_ts, 1 x_ts_cat, 2 x_cat, 3 x_cont,
//  4 u_ts_mask, 5 u_ts_act, 6 r_ts_idx,
//  7 u_cts_mask, 8 u_cts_act, 9 r_cts_idx,
// 10 u_cat_mask, 11 u_cat_act, 12 r_cat_val,
// 13 u_cont_mask, 14 u_cont_act, 15 r_cont_idx
// Output layout (f32): [masked_ts | masked_cts | masked_cat | masked_cont]
// ---------------------------------------------------------------------------
extern "C" void kernel_launch(void* const* d_in, const int* in_sizes, int n_in,
                              void* d_out, int out_size)
{
    const float* x_ts     = (const float*)d_in[0];
    const float* x_ts_cat = (const float*)d_in[1];
    const int*   x_cat    = (const int*)  d_in[2];
    const float* x_cont   = (const float*)d_in[3];

    const float* u_ts_mask  = (const float*)d_in[4];
    const float* u_ts_act   = (const float*)d_in[5];
    const int*   r_ts_idx   = (const int*)  d_in[6];
    const float* u_cts_mask = (const float*)d_in[7];
    const float* u_cts_act  = (const float*)d_in[8];
    const int*   r_cts_idx  = (const int*)  d_in[9];

    const float* u_cat_mask = (const float*)d_in[10];
    const float* u_cat_act  = (const float*)d_in[11];
    const int*   r_cat_val  = (const int*)  d_in[12];
    const float* u_cont_mask= (const float*)d_in[13];
    const float* u_cont_act = (const float*)d_in[14];
    const int*   r_cont_idx = (const int*)  d_in[15];

    float* out = (float*)d_out;
    const long TS_ELEMS  = (long)BS * C_TS  * T_LEN;   // 16,777,216
    const long CTS_ELEMS = (long)BS * C_CTS * T_LEN;   // 33,554,432
    float* out_ts   = out;
    float* out_cts  = out + TS_ELEMS;
    float* out_cat  = out + TS_ELEMS + CTS_ELEMS;
    float* out_cont = out_cat + (long)BS * N_CAT;

    const int threads = 256;
    {
        long groups = TS_ELEMS / 4;
        int blocks = (int)(groups / threads);
        mask_ts_kernel<<<blocks, threads>>>(x_ts, u_ts_mask, u_ts_act, r_ts_idx,
                                            out_ts, C_TS);
    }
    {
        long groups = CTS_ELEMS / 4;
        int blocks = (int)(groups / threads);
        mask_ts_kernel<<<blocks, threads>>>(x_ts_cat, u_cts_mask, u_cts_act, r_cts_idx,
                                            out_cts, C_CTS);
    }
    mask_static_kernel<<<1, 256>>>(x_cat, x_cont,
                                   u_cat_mask, u_cat_act, r_cat_val,
                                   u_cont_mask, u_cont_act, r_cont_idx,
                                   out_cat, out_cont);
}

// round 2
// speedup vs baseline: 1.0845x; 1.0845x over previous
#include <cuda_runtime.h>

// Problem constants (fixed by setup_inputs)
#define BS      64
#define C_TS    128
#define C_CTS   256
#define T_LEN   2048
#define N_CAT   32
#define N_CONT  64

#define MASK_P    0.15f
#define REPLACE_P 0.80f
#define RAND_HI   0.90f   // REPLACE_P + RANDOM_P

// Decision codes
#define CODE_KEEP  (-2)
#define CODE_ZERO  (-1)
// >= 0 : swap index within row

// Scratch: compact per-(b,t) decision codes (L2-resident, 512 KB each)
__device__ int g_code_ts [BS * T_LEN];
__device__ int g_code_cts[BS * T_LEN];

// ---------------------------------------------------------------------------
// Precompute kernel: encodes decisions for both TS tensors, and also handles
// the tiny static categorical/continuous outputs in its tail blocks.
// Grid: DEC_BLOCKS blocks for decisions + 1 block for static.
// ---------------------------------------------------------------------------
#define DEC_N      (BS * T_LEN)          // 131072 per tensor
#define DEC_THREADS 256
#define DEC_PER_T   4
#define DEC_BLOCKS  ((2 * DEC_N) / (DEC_THREADS * DEC_PER_T))   // 256

__device__ __forceinline__ int decide(float um, float ua, int ridx)
{
    if (um < MASK_P) {
        if (ua < REPLACE_P) return CODE_ZERO;
        if (ua < RAND_HI)   return ridx;
    }
    return CODE_KEEP;
}

__global__ void precompute_kernel(const float* __restrict__ u_ts_mask,
                                  const float* __restrict__ u_ts_act,
                                  const int*   __restrict__ r_ts_idx,
                                  const float* __restrict__ u_cts_mask,
                                  const float* __restrict__ u_cts_act,
                                  const int*   __restrict__ r_cts_idx,
                                  const int*   __restrict__ x_cat,
                                  const float* __restrict__ x_cont,
                                  const float* __restrict__ u_cat_mask,
                                  const float* __restrict__ u_cat_act,
                                  const int*   __restrict__ r_cat_val,
                                  const float* __restrict__ u_cont_mask,
                                  const float* __restrict__ u_cont_act,
                                  const int*   __restrict__ r_cont_idx,
                                  float* __restrict__ out_cat,
                                  float* __restrict__ out_cont)
{
    int blk = blockIdx.x;
    int tid = threadIdx.x;

    if (blk < DEC_BLOCKS) {
        // Decision encoding: first half -> ts, second half -> cts
        long base = ((long)blk * DEC_THREADS + tid) * DEC_PER_T;
        const float* um;
        const float* ua;
        const int*   ri;
        int* code;
        long off;
        if (base < DEC_N) { um = u_ts_mask;  ua = u_ts_act;  ri = r_ts_idx;  code = g_code_ts;  off = base; }
        else              { um = u_cts_mask; ua = u_cts_act; ri = r_cts_idx; code = g_code_cts; off = base - DEC_N; }

        float4 m4 = *(const float4*)(um + off);
        float4 a4 = *(const float4*)(ua + off);
        int4   r4 = *(const int4*)  (ri + off);

        int4 c4;
        c4.x = decide(m4.x, a4.x, r4.x);
        c4.y = decide(m4.y, a4.y, r4.y);
        c4.z = decide(m4.z, a4.z, r4.z);
        c4.w = decide(m4.w, a4.w, r4.w);
        *(int4*)(code + off) = c4;
        return;
    }

    // ---- static cat + cont (single tail block) ----
    __shared__ float means[N_CONT];
    if (tid < N_CONT) {
        float s = 0.0f;
        for (int b = 0; b < BS; b++) s += x_cont[b * N_CONT + tid];
        means[tid] = s * (1.0f / BS);
    }
    __syncthreads();

    for (int i = tid; i < BS * N_CAT; i += blockDim.x) {
        float um = u_cat_mask[i];
        float ua = u_cat_act[i];
        int v = x_cat[i];
        if (um < MASK_P) {
            if (ua < REPLACE_P)    v = 0;
            else if (ua < RAND_HI) v = r_cat_val[i];
        }
        out_cat[i] = (float)v;
    }

    for (int i = tid; i < BS * N_CONT; i += blockDim.x) {
        int j = i % N_CONT;
        float um = u_cont_mask[i];
        float ua = u_cont_act[i];
        float v = x_cont[i];
        if (um < MASK_P) {
            if (ua < REPLACE_P)    v = means[j];
            else if (ua < RAND_HI) v = x_cont[r_cont_idx[i] * N_CONT + j];
        }
        out_cont[i] = v;
    }
}

// ---------------------------------------------------------------------------
// Fused streaming kernel: TS blocks then CTS blocks in one grid.
// Thread = 4 consecutive t. Loads: code int4 (L2-hit) + x float4. Store float4.
// ---------------------------------------------------------------------------
#define TS_GROUPS   ((long)BS * C_TS  * T_LEN / 4)   // 4,194,304
#define CTS_GROUPS  ((long)BS * C_CTS * T_LEN / 4)   // 8,388,608
#define MAIN_THREADS 256
#define TS_BLOCKS   (TS_GROUPS  / MAIN_THREADS)      // 16384
#define CTS_BLOCKS  (CTS_GROUPS / MAIN_THREADS)      // 32768

__global__ void __launch_bounds__(MAIN_THREADS)
fused_mask_kernel(const float* __restrict__ x_ts,
                  float* __restrict__ out_ts,
                  const float* __restrict__ x_cts,
                  float* __restrict__ out_cts)
{
    long blk = blockIdx.x;
    const float* x;
    float* out;
    const int* code;
    int C;
    if (blk < TS_BLOCKS) {
        x = x_ts; out = out_ts; code = g_code_ts; C = C_TS;
    } else {
        blk -= TS_BLOCKS;
        x = x_cts; out = out_cts; code = g_code_cts; C = C_CTS;
    }

    long gid = blk * MAIN_THREADS + threadIdx.x;
    const int groups_per_row = T_LEN / 4;
    int  t0 = (int)(gid % groups_per_row) * 4;
    long bc = gid / groups_per_row;          // b*C + c
    int  b  = (int)(bc / C);

    const int4   c4 = *(const int4*)(code + (long)b * T_LEN + t0);
    const float* row = x + bc * T_LEN;
    float4 x4 = *(const float4*)(row + t0);

    float xv[4] = {x4.x, x4.y, x4.z, x4.w};
    int   cv[4] = {c4.x, c4.y, c4.z, c4.w};

    float o[4];
#pragma unroll
    for (int i = 0; i < 4; i++) {
        float v = xv[i];
        int c = cv[i];
        if (c != CODE_KEEP) {
            v = (c >= 0) ? __ldg(row + c) : 0.0f;
        }
        o[i] = v;
    }

    *(float4*)(out + bc * T_LEN + t0) = make_float4(o[0], o[1], o[2], o[3]);
}

// ---------------------------------------------------------------------------
// Launch
// ---------------------------------------------------------------------------
extern "C" void kernel_launch(void* const* d_in, const int* in_sizes, int n_in,
                              void* d_out, int out_size)
{
    const float* x_ts     = (const float*)d_in[0];
    const float* x_ts_cat = (const float*)d_in[1];
    const int*   x_cat    = (const int*)  d_in[2];
    const float* x_cont   = (const float*)d_in[3];

    const float* u_ts_mask  = (const float*)d_in[4];
    const float* u_ts_act   = (const float*)d_in[5];
    const int*   r_ts_idx   = (const int*)  d_in[6];
    const float* u_cts_mask = (const float*)d_in[7];
    const float* u_cts_act  = (const float*)d_in[8];
    const int*   r_cts_idx  = (const int*)  d_in[9];

    const float* u_cat_mask = (const float*)d_in[10];
    const float* u_cat_act  = (const float*)d_in[11];
    const int*   r_cat_val  = (const int*)  d_in[12];
    const float* u_cont_mask= (const float*)d_in[13];
    const float* u_cont_act = (const float*)d_in[14];
    const int*   r_cont_idx = (const int*)  d_in[15];

    float* out = (float*)d_out;
    const long TS_ELEMS  = (long)BS * C_TS  * T_LEN;   // 16,777,216
    const long CTS_ELEMS = (long)BS * C_CTS * T_LEN;   // 33,554,432
    float* out_ts   = out;
    float* out_cts  = out + TS_ELEMS;
    float* out_cat  = out + TS_ELEMS + CTS_ELEMS;
    float* out_cont = out_cat + (long)BS * N_CAT;

    precompute_kernel<<<DEC_BLOCKS + 1, DEC_THREADS>>>(
        u_ts_mask, u_ts_act, r_ts_idx,
        u_cts_mask, u_cts_act, r_cts_idx,
        x_cat, x_cont,
        u_cat_mask, u_cat_act, r_cat_val,
        u_cont_mask, u_cont_act, r_cont_idx,
        out_cat, out_cont);

    fused_mask_kernel<<<(int)(TS_BLOCKS + CTS_BLOCKS), MAIN_THREADS>>>(
        x_ts, out_ts, x_ts_cat, out_cts);
}

// round 3
// speedup vs baseline: 1.2556x; 1.1578x over previous
#include <cuda_runtime.h>

// Problem constants (fixed by setup_inputs)
#define BS      64
#define C_TS    128
#define C_CTS   256
#define T_LEN   2048
#define N_CAT   32
#define N_CONT  64

#define MASK_P    0.15f
#define REPLACE_P 0.80f
#define RAND_HI   0.90f   // REPLACE_P + RANDOM_P

// Decision codes (int16): -2 keep, -1 zero, >=0 swap index within row
#define CODE_KEEP  (-2)
#define CODE_ZERO  (-1)

// Scratch: compact per-(b,t) decision codes (256 KB each, L2-resident)
__device__ short g_code_ts [BS * T_LEN];
__device__ short g_code_cts[BS * T_LEN];

// ---------------------------------------------------------------------------
// Precompute: encode decisions for both TS tensors. Thread handles 8 t.
// ---------------------------------------------------------------------------
#define DEC_N        (BS * T_LEN)                       // 131072 per tensor
#define DEC_THREADS  256
#define DEC_PER_T    8
#define DEC_BLOCKS   ((2 * DEC_N) / (DEC_THREADS * DEC_PER_T))   // 128

__device__ __forceinline__ short decide(float um, float ua, int ridx)
{
    if (um < MASK_P) {
        if (ua < REPLACE_P) return (short)CODE_ZERO;
        if (ua < RAND_HI)   return (short)ridx;
    }
    return (short)CODE_KEEP;
}

__global__ void __launch_bounds__(DEC_THREADS)
precompute_kernel(const float* __restrict__ u_ts_mask,
                  const float* __restrict__ u_ts_act,
                  const int*   __restrict__ r_ts_idx,
                  const float* __restrict__ u_cts_mask,
                  const float* __restrict__ u_cts_act,
                  const int*   __restrict__ r_cts_idx)
{
    long base = ((long)blockIdx.x * DEC_THREADS + threadIdx.x) * DEC_PER_T;
    const float* um;
    const float* ua;
    const int*   ri;
    short* code;
    long off;
    if (base < DEC_N) { um = u_ts_mask;  ua = u_ts_act;  ri = r_ts_idx;  code = g_code_ts;  off = base; }
    else              { um = u_cts_mask; ua = u_cts_act; ri = r_cts_idx; code = g_code_cts; off = base - DEC_N; }

    float4 m0 = *(const float4*)(um + off);
    float4 m1 = *(const float4*)(um + off + 4);
    float4 a0 = *(const float4*)(ua + off);
    float4 a1 = *(const float4*)(ua + off + 4);
    int4   r0 = *(const int4*)  (ri + off);
    int4   r1 = *(const int4*)  (ri + off + 4);

    short c[8];
    c[0] = decide(m0.x, a0.x, r0.x);
    c[1] = decide(m0.y, a0.y, r0.y);
    c[2] = decide(m0.z, a0.z, r0.z);
    c[3] = decide(m0.w, a0.w, r0.w);
    c[4] = decide(m1.x, a1.x, r1.x);
    c[5] = decide(m1.y, a1.y, r1.y);
    c[6] = decide(m1.z, a1.z, r1.z);
    c[7] = decide(m1.w, a1.w, r1.w);

    int4 packed;
    packed.x = (int)(unsigned short)c[0] | ((int)(unsigned short)c[1] << 16);
    packed.y = (int)(unsigned short)c[2] | ((int)(unsigned short)c[3] << 16);
    packed.z = (int)(unsigned short)c[4] | ((int)(unsigned short)c[5] << 16);
    packed.w = (int)(unsigned short)c[6] | ((int)(unsigned short)c[7] << 16);
    *(int4*)(code + off) = packed;
}

// ---------------------------------------------------------------------------
// Fused streaming kernel: TS blocks, CTS blocks, + 1 static block.
// Thread = 8 consecutive t: 1×int4 code load, 2×float4 x loads, 2×float4 stores.
// ---------------------------------------------------------------------------
#define MAIN_THREADS 256
#define MAIN_PER_T   8
#define TS_BLOCKS    ((int)((long)BS * C_TS  * T_LEN / (MAIN_THREADS * MAIN_PER_T)))   // 8192
#define CTS_BLOCKS   ((int)((long)BS * C_CTS * T_LEN / (MAIN_THREADS * MAIN_PER_T)))   // 16384

__device__ __forceinline__ void process_ts(const float* __restrict__ x,
                                           float* __restrict__ out,
                                           const short* __restrict__ code,
                                           long blk, int logC)
{
    const int groups_per_row = T_LEN / MAIN_PER_T;    // 256
    long gid = blk * MAIN_THREADS + threadIdx.x;
    int  t0 = (int)(gid & (groups_per_row - 1)) * MAIN_PER_T;
    long bc = gid >> 8;                                // / groups_per_row
    int  b  = (int)(bc >> logC);

    // 8 codes in one int4
    int4 p = *(const int4*)(code + (long)b * T_LEN + t0);
    const float* row = x + bc * T_LEN;
    float4 x0 = *(const float4*)(row + t0);
    float4 x1 = *(const float4*)(row + t0 + 4);

    short c[8];
    c[0] = (short)(p.x & 0xFFFF); c[1] = (short)(p.x >> 16);
    c[2] = (short)(p.y & 0xFFFF); c[3] = (short)(p.y >> 16);
    c[4] = (short)(p.z & 0xFFFF); c[5] = (short)(p.z >> 16);
    c[6] = (short)(p.w & 0xFFFF); c[7] = (short)(p.w >> 16);

    float v[8] = {x0.x, x0.y, x0.z, x0.w, x1.x, x1.y, x1.z, x1.w};
#pragma unroll
    for (int i = 0; i < 8; i++) {
        short ci = c[i];
        if (ci != (short)CODE_KEEP) {
            v[i] = (ci >= 0) ? __ldg(row + ci) : 0.0f;
        }
    }

    float* orow = out + bc * T_LEN + t0;
    *(float4*)(orow)     = make_float4(v[0], v[1], v[2], v[3]);
    *(float4*)(orow + 4) = make_float4(v[4], v[5], v[6], v[7]);
}

__global__ void __launch_bounds__(MAIN_THREADS)
fused_mask_kernel(const float* __restrict__ x_ts,
                  float* __restrict__ out_ts,
                  const float* __restrict__ x_cts,
                  float* __restrict__ out_cts,
                  const int*   __restrict__ x_cat,
                  const float* __restrict__ x_cont,
                  const float* __restrict__ u_cat_mask,
                  const float* __restrict__ u_cat_act,
                  const int*   __restrict__ r_cat_val,
                  const float* __restrict__ u_cont_mask,
                  const float* __restrict__ u_cont_act,
                  const int*   __restrict__ r_cont_idx,
                  float* __restrict__ out_cat,
                  float* __restrict__ out_cont)
{
    long blk = blockIdx.x;
    if (blk < TS_BLOCKS) {
        process_ts(x_ts, out_ts, g_code_ts, blk, 7);           // logC = log2(128)
        return;
    }
    blk -= TS_BLOCKS;
    if (blk < CTS_BLOCKS) {
        process_ts(x_cts, out_cts, g_code_cts, blk, 8);        // logC = log2(256)
        return;
    }

    // ---- static cat + cont (single tail block, 256 threads) ----
    int tid = threadIdx.x;
    __shared__ float partial[4][N_CONT];
    __shared__ float means[N_CONT];

    {
        int j = tid & (N_CONT - 1);        // column
        int chunk = tid >> 6;              // 0..3, 16 rows each
        float s = 0.0f;
        for (int b = chunk * 16; b < chunk * 16 + 16; b++)
            s += x_cont[b * N_CONT + j];
        partial[chunk][j] = s;
    }
    __syncthreads();
    if (tid < N_CONT) {
        means[tid] = (partial[0][tid] + partial[1][tid] +
                      partial[2][tid] + partial[3][tid]) * (1.0f / BS);
    }
    __syncthreads();

    // categorical: BS*N_CAT = 2048 elements
    for (int i = tid; i < BS * N_CAT; i += blockDim.x) {
        float um = u_cat_mask[i];
        float ua = u_cat_act[i];
        int v = x_cat[i];
        if (um < MASK_P) {
            if (ua < REPLACE_P)    v = 0;
            else if (ua < RAND_HI) v = r_cat_val[i];
        }
        out_cat[i] = (float)v;
    }

    // continuous: BS*N_CONT = 4096 elements
    for (int i = tid; i < BS * N_CONT; i += blockDim.x) {
        int j = i & (N_CONT - 1);
        float um = u_cont_mask[i];
        float ua = u_cont_act[i];
        float v = x_cont[i];
        if (um < MASK_P) {
            if (ua < REPLACE_P)    v = means[j];
            else if (ua < RAND_HI) v = x_cont[r_cont_idx[i] * N_CONT + j];
        }
        out_cont[i] = v;
    }
}

// ---------------------------------------------------------------------------
// Launch
// ---------------------------------------------------------------------------
extern "C" void kernel_launch(void* const* d_in, const int* in_sizes, int n_in,
                              void* d_out, int out_size)
{
    const float* x_ts     = (const float*)d_in[0];
    const float* x_ts_cat = (const float*)d_in[1];
    const int*   x_cat    = (const int*)  d_in[2];
    const float* x_cont   = (const float*)d_in[3];

    const float* u_ts_mask  = (const float*)d_in[4];
    const float* u_ts_act   = (const float*)d_in[5];
    const int*   r_ts_idx   = (const int*)  d_in[6];
    const float* u_cts_mask = (const float*)d_in[7];
    const float* u_cts_act  = (const float*)d_in[8];
    const int*   r_cts_idx  = (const int*)  d_in[9];

    const float* u_cat_mask = (const float*)d_in[10];
    const float* u_cat_act  = (const float*)d_in[11];
    const int*   r_cat_val  = (const int*)  d_in[12];
    const float* u_cont_mask= (const float*)d_in[13];
    const float* u_cont_act = (const float*)d_in[14];
    const int*   r_cont_idx = (const int*)  d_in[15];

    float* out = (float*)d_out;
    const long TS_ELEMS  = (long)BS * C_TS  * T_LEN;   // 16,777,216
    const long CTS_ELEMS = (long)BS * C_CTS * T_LEN;   // 33,554,432
    float* out_ts   = out;
    float* out_cts  = out + TS_ELEMS;
    float* out_cat  = out + TS_ELEMS + CTS_ELEMS;
    float* out_cont = out_cat + (long)BS * N_CAT;

    precompute_kernel<<<DEC_BLOCKS, DEC_THREADS>>>(
        u_ts_mask, u_ts_act, r_ts_idx,
        u_cts_mask, u_cts_act, r_cts_idx);

    fused_mask_kernel<<<TS_BLOCKS + CTS_BLOCKS + 1, MAIN_THREADS>>>(
        x_ts, out_ts, x_ts_cat, out_cts,
        x_cat, x_cont,
        u_cat_mask, u_cat_act, r_cat_val,
        u_cont_mask, u_cont_act, r_cont_idx,
        out_cat, out_cont);
}